// round 10
// baseline (speedup 1.0000x reference)
#include <cuda_runtime.h>
#include <cuda_bf16.h>
#include <cstdint>

#define BATCH 4
#define NPTS  4096
#define CIN   64
#define COUT  128
#define KNN   16
#define KSPLIT 4
#define PTSB  8            // points per fuse block
#define ROWS  128          // PTSB * KNN
#define APAD  136          // bf16 per padded A/B row
#define AW    68           // u32 words per padded row

typedef unsigned long long u64;
typedef unsigned int u32;

// ---------------- device scratch (no allocations allowed) -------------------
__device__ int   g_idx[BATCH * NPTS * KNN];
__device__ float g_knd[2 * BATCH * NPTS * KNN];
__device__ int   g_kni[2 * BATCH * NPTS * KNN];
__device__ float g_featc[BATCH * NPTS * COUT];
__device__ float g_featn[BATCH * NPTS * COUT];
__device__ float g_fcw[BATCH * NPTS * COUT];   // featc@Wa1 + (bp2@Wa1 + ba1)
__device__ float g_fnw[BATCH * NPTS * COUT];   // featn@Wa1
__device__ float g_u[BATCH * NPTS * COUT];     // sum_k w_k P1_k
__device__ float g_wa2ws[COUT];
__device__ float g_bvec[COUT];
__device__ __align__(16) __nv_bfloat16 gWPA_hi[128 * APAD];  // (Wp2@Wa1)^T image
__device__ __align__(16) __nv_bfloat16 gWPA_lo[128 * APAD];

// ---------------- helpers ----------------------------------------------------
__device__ __forceinline__ void mma_bf16(float* c,
                                         u32 a0, u32 a1, u32 a2, u32 a3,
                                         u32 b0, u32 b1) {
    asm volatile(
        "mma.sync.aligned.m16n8k16.row.col.f32.bf16.bf16.f32 "
        "{%0,%1,%2,%3}, {%4,%5,%6,%7}, {%8,%9}, {%0,%1,%2,%3};"
        : "+f"(c[0]), "+f"(c[1]), "+f"(c[2]), "+f"(c[3])
        : "r"(a0), "r"(a1), "r"(a2), "r"(a3), "r"(b0), "r"(b1));
}
__device__ __forceinline__ void ldsm_x4(u32* r, u32 addr) {
    asm volatile("ldmatrix.sync.aligned.m8n8.x4.shared.b16 {%0,%1,%2,%3}, [%4];"
        : "=r"(r[0]), "=r"(r[1]), "=r"(r[2]), "=r"(r[3]) : "r"(addr));
}
__device__ __forceinline__ u32 smem_u32(const void* p) {
    u32 a;
    asm("{ .reg .u64 t; cvta.to.shared.u64 t, %1; cvt.u32.u64 %0, t; }"
        : "=r"(a) : "l"(p));
    return a;
}
__device__ __forceinline__ void split2(float x, float y, u32& hi, u32& lo) {
    __nv_bfloat16 hx = __float2bfloat16(x);
    __nv_bfloat16 hy = __float2bfloat16(y);
    __nv_bfloat162 hp; hp.x = hx; hp.y = hy;
    __nv_bfloat162 lp;
    lp.x = __float2bfloat16(x - __bfloat162float(hx));
    lp.y = __float2bfloat16(y - __bfloat162float(hy));
    hi = *(u32*)&hp; lo = *(u32*)&lp;
}

// ---------------- fuse SMEM layout (bytes) -----------------------------------
#define OFF_SIDX   0
#define OFF_SPD    512
#define OFF_SFC    2048
#define OFF_SFCW   6144
#define OFF_WV     10240
#define OFF_SPART  10752
#define OFF_SW     11776
#define OFF_P1F    12288
#define OFF_AHI    77824
#define OFF_ALO    112640
#define OFF_BHI    147456
#define OFF_BLO    182272
#define SMEM_TOTAL 217088
#define DLO        34816

// ---------------------------------------------------------------------------
// prep: blocks 0..63 build WPA = Wp2@Wa1 bf16 hi/lo N-major images;
// block 64: wa2ws fold + bvec = bp2@Wa1 + ba1.
// ---------------------------------------------------------------------------
__global__ void prep_kernel(const float* __restrict__ Wp2,
                            const float* __restrict__ Wa1,
                            const float* __restrict__ Wa2,
                            const float* __restrict__ Ws,
                            const float* __restrict__ bp2,
                            const float* __restrict__ ba1) {
    const int blk = blockIdx.x;
    const int tid = threadIdx.x;
    if (blk == 64) {
        if (tid < COUT) {
            float s = 0.0f;
#pragma unroll 8
            for (int j = 0; j < COUT; j++) s = fmaf(Wa2[tid * COUT + j], Ws[j], s);
            g_wa2ws[tid] = s;
        } else {
            const int n = tid - 128;
            float s = ba1[n];
#pragma unroll 8
            for (int j = 0; j < COUT; j++) s = fmaf(bp2[j], Wa1[j * COUT + n], s);
            g_bvec[n] = s;
        }
        return;
    }
    const int idx = blk * 256 + tid;       // 0..16383
    const int n = idx & 127;
    const int k = idx >> 7;
    float v = 0.0f;
#pragma unroll 8
    for (int j = 0; j < COUT; j++) v = fmaf(Wp2[k * COUT + j], Wa1[j * COUT + n], v);
    const int o = n * APAD + k;
    __nv_bfloat16 hi = __float2bfloat16(v);
    gWPA_hi[o] = hi;
    gWPA_lo[o] = __float2bfloat16(v - __bfloat162float(hi));
}

// ---------------------------------------------------------------------------
// knn: blockIdx.z = candidate half; batch-of-8 max filter.
// ---------------------------------------------------------------------------
__global__ void knn_kernel(const float* __restrict__ pos) {
    const int b    = blockIdx.y;
    const int half = blockIdx.z;
    const int lane = threadIdx.x & 31;
    const int w    = threadIdx.x >> 5;
    const int q    = blockIdx.x * 32 + lane;
    const float* posb = pos + (size_t)b * NPTS * 3;

    const float qx = posb[q * 3 + 0];
    const float qy = posb[q * 3 + 1];
    const float qz = posb[q * 3 + 2];

    float bd[KNN];
    int   bi[KNN];
#pragma unroll
    for (int k = 0; k < KNN; k++) { bd[k] = -1e30f; bi[k] = 0; }

    __shared__ float4 tile[KSPLIT][128];
    __shared__ float  sd[KSPLIT][32][KNN];
    __shared__ int    si[KSPLIT][32][KNN];

    const int base = half * 2048 + w * 512;
    for (int t = 0; t < 512; t += 128) {
        __syncwarp();
#pragma unroll
        for (int u = 0; u < 4; u++) {
            const int j = base + t + lane * 4 + u;
            const float x = posb[j * 3 + 0];
            const float y = posb[j * 3 + 1];
            const float z = posb[j * 3 + 2];
            tile[w][lane * 4 + u] = make_float4(x, y, z, -0.5f * (x * x + y * y + z * z));
        }
        __syncwarp();
#pragma unroll 2
        for (int jj = 0; jj < 128; jj += 8) {
            float kk[8];
#pragma unroll
            for (int u = 0; u < 8; u++) {
                const float4 c = tile[w][jj + u];
                kk[u] = fmaf(qx, c.x, fmaf(qy, c.y, fmaf(qz, c.z, c.w)));
            }
            float mx = fmaxf(kk[0], kk[1]);
            mx = fmaxf(mx, fmaxf(kk[2], kk[3]));
            mx = fmaxf(mx, fmaxf(kk[4], kk[5]));
            mx = fmaxf(mx, fmaxf(kk[6], kk[7]));
            if (mx > bd[KNN - 1]) {
#pragma unroll
                for (int u = 0; u < 8; u++) {
                    if (kk[u] > bd[KNN - 1]) {
                        bd[KNN - 1] = kk[u];
                        bi[KNN - 1] = base + t + jj + u;
#pragma unroll
                        for (int s = KNN - 1; s > 0; --s) {
                            if (bd[s] > bd[s - 1]) {
                                const float td = bd[s]; bd[s] = bd[s - 1]; bd[s - 1] = td;
                                const int   ti = bi[s]; bi[s] = bi[s - 1]; bi[s - 1] = ti;
                            }
                        }
                    }
                }
            }
        }
    }
#pragma unroll
    for (int k = 0; k < KNN; k++) { sd[w][lane][k] = bd[k]; si[w][lane][k] = bi[k]; }
    __syncthreads();

    if (threadIdx.x < 32) {
        const int t = threadIdx.x;
        int pp[KSPLIT];
#pragma unroll
        for (int s = 0; s < KSPLIT; s++) pp[s] = 0;
        const size_t qg = (size_t)b * NPTS + blockIdx.x * 32 + t;
        float* outd = g_knd + ((size_t)half * BATCH * NPTS + qg) * KNN;
        int*   outi = g_kni + ((size_t)half * BATCH * NPTS + qg) * KNN;
#pragma unroll
        for (int k = 0; k < KNN; k++) {
            float bestd = -1e31f; int bests = 0, besti = 0x7fffffff;
#pragma unroll
            for (int s = 0; s < KSPLIT; s++) {
                if (pp[s] < KNN) {
                    const float dv = sd[s][t][pp[s]];
                    const int   iv = si[s][t][pp[s]];
                    if (dv > bestd || (dv == bestd && iv < besti)) {
                        bestd = dv; besti = iv; bests = s;
                    }
                }
            }
            outd[k] = bestd; outi[k] = besti;
            pp[bests]++;
        }
    }
}

__global__ void knn_merge_kernel() {
    const size_t q = (size_t)blockIdx.x * blockDim.x + threadIdx.x;
    const float* d0 = g_knd + q * KNN;
    const float* d1 = g_knd + ((size_t)BATCH * NPTS + q) * KNN;
    const int*   i0 = g_kni + q * KNN;
    const int*   i1 = g_kni + ((size_t)BATCH * NPTS + q) * KNN;
    int p0 = 0, p1 = 0;
    int* outp = g_idx + q * KNN;
#pragma unroll
    for (int k = 0; k < KNN; k++) {
        const float a = d0[p0];
        const float c = d1[p1];
        if (a >= c) { outp[k] = i0[p0]; p0++; }
        else        { outp[k] = i1[p1]; p1++; }
    }
}

// ---------------------------------------------------------------------------
// linear: feat_c = x@Wc+bc ; feat_n = x@Wn+bn  (K=64)
// ---------------------------------------------------------------------------
__global__ void __launch_bounds__(128)
linear_kernel(const float* __restrict__ x,
              const float* __restrict__ Wc, const float* __restrict__ bc,
              const float* __restrict__ Wn, const float* __restrict__ bn) {
    const int row0 = blockIdx.x * 32;
    const int tid  = threadIdx.x;
    const int lane = tid & 31;
    const int w    = tid >> 5;
    const int r0   = w * 8;
    const int c4   = lane * 4;

    __shared__ float xs[32 * CIN];
    {
        const float4* src = (const float4*)(x + (size_t)row0 * CIN);
        float4* dst = (float4*)xs;
#pragma unroll
        for (int i = 0; i < 4; i++) dst[tid + i * 128] = src[tid + i * 128];
    }
    __syncthreads();

#pragma unroll
    for (int pass = 0; pass < 2; pass++) {
        const float* W  = pass ? Wn : Wc;
        const float* bb = pass ? bn : bc;
        float* G = pass ? g_featn : g_featc;

        float acc[8][4];
        const float4 b4 = *(const float4*)(bb + c4);
#pragma unroll
        for (int i = 0; i < 8; i++) {
            acc[i][0] = b4.x; acc[i][1] = b4.y; acc[i][2] = b4.z; acc[i][3] = b4.w;
        }
#pragma unroll 4
        for (int k0 = 0; k0 < CIN; k0 += 4) {
            float4 ww[4];
#pragma unroll
            for (int kk = 0; kk < 4; kk++)
                ww[kk] = *(const float4*)(W + (k0 + kk) * COUT + c4);
#pragma unroll
            for (int i = 0; i < 8; i++) {
                const float4 a = *(const float4*)(xs + (r0 + i) * CIN + k0);
                acc[i][0] = fmaf(a.x, ww[0].x, acc[i][0]);
                acc[i][0] = fmaf(a.y, ww[1].x, acc[i][0]);
                acc[i][0] = fmaf(a.z, ww[2].x, acc[i][0]);
                acc[i][0] = fmaf(a.w, ww[3].x, acc[i][0]);
                acc[i][1] = fmaf(a.x, ww[0].y, acc[i][1]);
                acc[i][1] = fmaf(a.y, ww[1].y, acc[i][1]);
                acc[i][1] = fmaf(a.z, ww[2].y, acc[i][1]);
                acc[i][1] = fmaf(a.w, ww[3].y, acc[i][1]);
                acc[i][2] = fmaf(a.x, ww[0].z, acc[i][2]);
                acc[i][2] = fmaf(a.y, ww[1].z, acc[i][2]);
                acc[i][2] = fmaf(a.z, ww[2].z, acc[i][2]);
                acc[i][2] = fmaf(a.w, ww[3].z, acc[i][2]);
                acc[i][3] = fmaf(a.x, ww[0].w, acc[i][3]);
                acc[i][3] = fmaf(a.y, ww[1].w, acc[i][3]);
                acc[i][3] = fmaf(a.z, ww[2].w, acc[i][3]);
                acc[i][3] = fmaf(a.w, ww[3].w, acc[i][3]);
            }
        }
#pragma unroll
        for (int i = 0; i < 8; i++) {
            float4 o; o.x = acc[i][0]; o.y = acc[i][1]; o.z = acc[i][2]; o.w = acc[i][3];
            *(float4*)(G + (size_t)(row0 + r0 + i) * COUT + c4) = o;
        }
    }
}

// ---------------------------------------------------------------------------
// linw: FCW = featc@Wa1 + bvec ; FNW = featn@Wa1  (K=128)
// ---------------------------------------------------------------------------
__global__ void __launch_bounds__(128)
linw_kernel(const float* __restrict__ Wa1) {
    const int row0 = blockIdx.x * 32;
    const int tid  = threadIdx.x;
    const int lane = tid & 31;
    const int w    = tid >> 5;
    const int r0   = w * 8;
    const int c4   = lane * 4;

    __shared__ float xs[32 * COUT];

#pragma unroll
    for (int pass = 0; pass < 2; pass++) {
        const float* X = pass ? g_featn : g_featc;
        float* G = pass ? g_fnw : g_fcw;

        {
            const float4* src = (const float4*)(X + (size_t)row0 * COUT);
            float4* dst = (float4*)xs;
#pragma unroll
            for (int i = 0; i < 8; i++) dst[tid + i * 128] = src[tid + i * 128];
        }
        __syncthreads();

        float acc[8][4];
        if (pass == 0) {
            const float4 b4 = *(const float4*)(g_bvec + c4);
#pragma unroll
            for (int i = 0; i < 8; i++) {
                acc[i][0] = b4.x; acc[i][1] = b4.y; acc[i][2] = b4.z; acc[i][3] = b4.w;
            }
        } else {
#pragma unroll
            for (int i = 0; i < 8; i++) {
                acc[i][0] = 0.f; acc[i][1] = 0.f; acc[i][2] = 0.f; acc[i][3] = 0.f;
            }
        }
#pragma unroll 4
        for (int k0 = 0; k0 < COUT; k0 += 4) {
            float4 ww[4];
#pragma unroll
            for (int kk = 0; kk < 4; kk++)
                ww[kk] = *(const float4*)(Wa1 + (k0 + kk) * COUT + c4);
#pragma unroll
            for (int i = 0; i < 8; i++) {
                const float4 a = *(const float4*)(xs + (r0 + i) * COUT + k0);
                acc[i][0] = fmaf(a.x, ww[0].x, acc[i][0]);
                acc[i][0] = fmaf(a.y, ww[1].x, acc[i][0]);
                acc[i][0] = fmaf(a.z, ww[2].x, acc[i][0]);
                acc[i][0] = fmaf(a.w, ww[3].x, acc[i][0]);
                acc[i][1] = fmaf(a.x, ww[0].y, acc[i][1]);
                acc[i][1] = fmaf(a.y, ww[1].y, acc[i][1]);
                acc[i][1] = fmaf(a.z, ww[2].y, acc[i][1]);
                acc[i][1] = fmaf(a.w, ww[3].y, acc[i][1]);
                acc[i][2] = fmaf(a.x, ww[0].z, acc[i][2]);
                acc[i][2] = fmaf(a.y, ww[1].z, acc[i][2]);
                acc[i][2] = fmaf(a.z, ww[2].z, acc[i][2]);
                acc[i][2] = fmaf(a.w, ww[3].z, acc[i][2]);
                acc[i][3] = fmaf(a.x, ww[0].w, acc[i][3]);
                acc[i][3] = fmaf(a.y, ww[1].w, acc[i][3]);
                acc[i][3] = fmaf(a.z, ww[2].w, acc[i][3]);
                acc[i][3] = fmaf(a.w, ww[3].w, acc[i][3]);
            }
        }
#pragma unroll
        for (int i = 0; i < 8; i++) {
            float4 o; o.x = acc[i][0]; o.y = acc[i][1]; o.z = acc[i][2]; o.w = acc[i][3];
            *(float4*)(G + (size_t)(row0 + r0 + i) * COUT + c4) = o;
        }
        __syncthreads();
    }
}

// ---------------------------------------------------------------------------
// gemm pass (validated in R8): warp (wm, wn) computes rows [32wm,32wm+32) x
// cols [64wn,64wn+64), K=128, ldmatrix.x4 + 3-term bf16 hi/lo mma.sync.
// ---------------------------------------------------------------------------
__device__ __forceinline__ void gemm_pass(u32 sb, int wm, int wn, int lane,
                                          float (&acc)[2][8][4]) {
    const int arow = wm * 32 + ((lane >> 3) & 1) * 8 + (lane & 7);
    const int ak   = (lane >> 4) * 8;
    u32 aB = sb + OFF_AHI + (u32)(arow * (AW * 4) + ak * 2);
    const int nrow = wn * 64 + (lane >> 4) * 8 + (lane & 7);
    const int bk   = ((lane >> 3) & 1) * 8;
    u32 bB = sb + OFF_BHI + (u32)(nrow * (AW * 4) + bk * 2);
#pragma unroll
    for (int kt = 0; kt < 8; kt++) {
        u32 ah0[4], al0[4], ah1[4], al1[4];
        ldsm_x4(ah0, aB);
        ldsm_x4(al0, aB + DLO);
        ldsm_x4(ah1, aB + 16 * (AW * 4));
        ldsm_x4(al1, aB + 16 * (AW * 4) + DLO);
#pragma unroll
        for (int p = 0; p < 4; p++) {
            u32 bh[4], bl[4];
            const u32 ba = bB + p * 16 * (AW * 4);
            ldsm_x4(bh, ba);
            ldsm_x4(bl, ba + DLO);
            mma_bf16(acc[0][2*p],   ah0[0],ah0[1],ah0[2],ah0[3], bh[0],bh[1]);
            mma_bf16(acc[0][2*p],   ah0[0],ah0[1],ah0[2],ah0[3], bl[0],bl[1]);
            mma_bf16(acc[0][2*p],   al0[0],al0[1],al0[2],al0[3], bh[0],bh[1]);
            mma_bf16(acc[0][2*p+1], ah0[0],ah0[1],ah0[2],ah0[3], bh[2],bh[3]);
            mma_bf16(acc[0][2*p+1], ah0[0],ah0[1],ah0[2],ah0[3], bl[2],bl[3]);
            mma_bf16(acc[0][2*p+1], al0[0],al0[1],al0[2],al0[3], bh[2],bh[3]);
            mma_bf16(acc[1][2*p],   ah1[0],ah1[1],ah1[2],ah1[3], bh[0],bh[1]);
            mma_bf16(acc[1][2*p],   ah1[0],ah1[1],ah1[2],ah1[3], bl[0],bl[1]);
            mma_bf16(acc[1][2*p],   al1[0],al1[1],al1[2],al1[3], bh[0],bh[1]);
            mma_bf16(acc[1][2*p+1], ah1[0],ah1[1],ah1[2],ah1[3], bh[2],bh[3]);
            mma_bf16(acc[1][2*p+1], ah1[0],ah1[1],ah1[2],ah1[3], bl[2],bl[3]);
            mma_bf16(acc[1][2*p+1], al1[0],al1[1],al1[2],al1[3], bh[2],bh[3]);
        }
        aB += 32;
        bB += 32;
    }
}

// ---------------------------------------------------------------------------
// fuse: 8 points/block, 256 threads. ONE pair GEMM: acc = P1 @ WPA.
// Scores from acc + FCW - FNW; softmax; aggregate fc + sum(w fn) -> out,
// u = sum(w P1) -> g_u.
// ---------------------------------------------------------------------------
__global__ void __launch_bounds__(256, 1)
fuse_kernel(const float* __restrict__ pos,
            const float* __restrict__ Wp1, const float* __restrict__ bp1,
            float* __restrict__ out) {
    extern __shared__ char smem[];
    const u32 sb   = smem_u32(smem);
    const int tid  = threadIdx.x;
    const int lane = tid & 31;
    const int w    = tid >> 5;
    const int wm   = w & 3;
    const int wn   = w >> 2;
    const int p0g  = blockIdx.x * PTSB;
    const int b    = p0g >> 12;

    int*   sidx  = (int*)(smem + OFF_SIDX);
    float* spd   = (float*)(smem + OFF_SPD);
    float* sfc   = (float*)(smem + OFF_SFC);
    float* sfcw  = (float*)(smem + OFF_SFCW);
    float* swv   = (float*)(smem + OFF_WV);
    float* spart = (float*)(smem + OFF_SPART);
    float* sw    = (float*)(smem + OFF_SW);
    float* sP1   = (float*)(smem + OFF_P1F);
    u32* sAhi = (u32*)(smem + OFF_AHI);
    u32* sAlo = (u32*)(smem + OFF_ALO);
    u32* sBhi = (u32*)(smem + OFF_BHI);
    u32* sBlo = (u32*)(smem + OFF_BLO);

    // --- loads -------------------------------------------------------------
    if (tid < ROWS) sidx[tid] = g_idx[(size_t)p0g * KNN + tid];
    if (tid < COUT) swv[tid] = g_wa2ws[tid];
    {
        const uint4* h = (const uint4*)gWPA_hi;
        const uint4* l = (const uint4*)gWPA_lo;
        uint4* dh = (uint4*)sBhi;
        uint4* dl = (uint4*)sBlo;
#pragma unroll
        for (int i = 0; i < 8; i++) { dh[tid + i * 256] = h[tid + i * 256];
                                      dl[tid + i * 256] = l[tid + i * 256]; }
        if (tid < 128) { dh[tid + 2048] = h[tid + 2048];
                         dl[tid + 2048] = l[tid + 2048]; }
    }
    {
        const float4* s1 = (const float4*)(g_featc + (size_t)p0g * COUT);
        const float4* s2 = (const float4*)(g_fcw + (size_t)p0g * COUT);
        ((float4*)sfc)[tid]  = s1[tid];
        ((float4*)sfcw)[tid] = s2[tid];
    }
    __syncthreads();
    if (tid < ROWS) {
        const int r = tid;
        const int p = r >> 4;
        const int j = sidx[r];
        const float* qp = pos + (size_t)(p0g + p) * 3;
        const float* np = pos + ((size_t)(b << 12) + j) * 3;
        spd[r * 3 + 0] = qp[0] - np[0];
        spd[r * 3 + 1] = qp[1] - np[1];
        spd[r * 3 + 2] = qp[2] - np[2];
    }
    __syncthreads();

    // --- P1 = relu(spd @ Wp1 + bp1): fp32 to sP1, bf16 hi/lo to sA ---------
    {
        const int kp = tid & 63;
        const float2 w0 = *(const float2*)(Wp1 + 0 * COUT + 2 * kp);
        const float2 w1 = *(const float2*)(Wp1 + 1 * COUT + 2 * kp);
        const float2 w2 = *(const float2*)(Wp1 + 2 * COUT + 2 * kp);
        const float2 bb = *(const float2*)(bp1 + 2 * kp);
        for (int r = tid >> 6; r < ROWS; r += 4) {
            const float d0 = spd[r * 3 + 0];
            const float d1 = spd[r * 3 + 1];
            const float d2 = spd[r * 3 + 2];
            float va = fmaxf(fmaf(d0, w0.x, fmaf(d1, w1.x, fmaf(d2, w2.x, bb.x))), 0.0f);
            float vb = fmaxf(fmaf(d0, w0.y, fmaf(d1, w1.y, fmaf(d2, w2.y, bb.y))), 0.0f);
            u32 hi, lo;
            split2(va, vb, hi, lo);
            sAhi[r * AW + kp] = hi;
            sAlo[r * AW + kp] = lo;
            float2 pf; pf.x = va; pf.y = vb;
            *(float2*)(sP1 + r * COUT + 2 * kp) = pf;
        }
    }
    __syncthreads();

    // --- GEMM: acc = P1 @ WPA ---------------------------------------------
    float acc[2][8][4];
#pragma unroll
    for (int mt = 0; mt < 2; mt++)
#pragma unroll
        for (int nt = 0; nt < 8; nt++) {
            acc[mt][nt][0] = 0.f; acc[mt][nt][1] = 0.f;
            acc[mt][nt][2] = 0.f; acc[mt][nt][3] = 0.f;
        }
    gemm_pass(sb, wm, wn, lane, acc);

    // --- score epilogue: a1pre = acc + FCW[i] - FNW[j]; partials -----------
#pragma unroll
    for (int mt = 0; mt < 2; mt++) {
        const int r1 = wm * 32 + mt * 16 + (lane >> 2);
        const int r2 = r1 + 8;
        const int j1 = sidx[r1], j2 = sidx[r2];
        const float* fnw1 = g_fnw + ((size_t)(b << 12) + j1) * COUT;
        const float* fnw2 = g_fnw + ((size_t)(b << 12) + j2) * COUT;
        const float* fcw1 = sfcw + (r1 >> 4) * COUT;
        const float* fcw2 = sfcw + (r2 >> 4) * COUT;
        float s1 = 0.0f, s2 = 0.0f;
#pragma unroll
        for (int nt = 0; nt < 8; nt++) {
            const int col = wn * 64 + nt * 8 + (lane & 3) * 2;
            const float2 wv = *(const float2*)(swv + col);
            {
                const float2 fw = *(const float2*)(fcw1 + col);
                const float2 fn = *(const float2*)(fnw1 + col);
                s1 = fmaf(fmaxf(acc[mt][nt][0] + fw.x - fn.x, 0.0f), wv.x, s1);
                s1 = fmaf(fmaxf(acc[mt][nt][1] + fw.y - fn.y, 0.0f), wv.y, s1);
            }
            {
                const float2 fw = *(const float2*)(fcw2 + col);
                const float2 fn = *(const float2*)(fnw2 + col);
                s2 = fmaf(fmaxf(acc[mt][nt][2] + fw.x - fn.x, 0.0f), wv.x, s2);
                s2 = fmaf(fmaxf(acc[mt][nt][3] + fw.y - fn.y, 0.0f), wv.y, s2);
            }
        }
        s1 += __shfl_xor_sync(0xffffffffu, s1, 1);
        s1 += __shfl_xor_sync(0xffffffffu, s1, 2);
        s2 += __shfl_xor_sync(0xffffffffu, s2, 1);
        s2 += __shfl_xor_sync(0xffffffffu, s2, 2);
        if ((lane & 3) == 0) {
            spart[wn * 128 + r1] = s1;
            spart[wn * 128 + r2] = s2;
        }
    }
    __syncthreads();

    // --- softmax weights ---------------------------------------------------
    {
        const int p = tid >> 5;
        float sc[KNN];
        float m = -1e30f;
#pragma unroll
        for (int k = 0; k < KNN; k++) {
            const int r = p * KNN + k;
            sc[k] = spart[r] + spart[128 + r];
            m = fmaxf(m, sc[k]);
        }
        float s = 0.0f;
#pragma unroll
        for (int k = 0; k < KNN; k++) { sc[k] = expf(sc[k] - m); s += sc[k]; }
        const float inv = 1.0f / s;
        if (lane < KNN) sw[p * KNN + lane] = sc[lane] * inv;
    }
    __syncthreads();

    // --- aggregation: out = fc + sum(w fn); u = sum(w P1) ------------------
    {
        const int p  = tid >> 5;
        const int c4 = lane * 4;
        float4 g4 = *(const float4*)(sfc + p * COUT + c4);
        float4 u4 = make_float4(0.f, 0.f, 0.f, 0.f);
#pragma unroll
        for (int k = 0; k < KNN; k++) {
            const float wk = sw[p * KNN + k];
            const int r = p * KNN + k;
            const int j = sidx[r];
            const float4 fn = *(const float4*)(g_featn + ((size_t)(b << 12) + j) * COUT + c4);
            g4.x = fmaf(wk, fn.x, g4.x);
            g4.y = fmaf(wk, fn.y, g4.y);
            g4.z = fmaf(wk, fn.z, g4.z);
            g4.w = fmaf(wk, fn.w, g4.w);
            const float4 pv = *(const float4*)(sP1 + r * COUT + c4);
            u4.x = fmaf(wk, pv.x, u4.x);
            u4.y = fmaf(wk, pv.y, u4.y);
            u4.z = fmaf(wk, pv.z, u4.z);
            u4.w = fmaf(wk, pv.w, u4.w);
        }
        *(float4*)(out + (size_t)(p0g + p) * COUT + c4) = g4;
        *(float4*)(g_u + (size_t)(p0g + p) * COUT + c4) = u4;
    }
}

// ---------------------------------------------------------------------------
// final: out += u @ Wp2 + bp2   (K=128 dense)
// ---------------------------------------------------------------------------
__global__ void __launch_bounds__(128)
final_kernel(const float* __restrict__ Wp2, const float* __restrict__ bp2,
             float* __restrict__ out) {
    const int row0 = blockIdx.x * 32;
    const int tid  = threadIdx.x;
    const int lane = tid & 31;
    const int w    = tid >> 5;
    const int r0   = w * 8;
    const int c4   = lane * 4;

    __shared__ float us[32 * COUT];
    {
        const float4* src = (const float4*)(g_u + (size_t)row0 * COUT);
        float4* dst = (float4*)us;
#pragma unroll
        for (int i = 0; i < 8; i++) dst[tid + i * 128] = src[tid + i * 128];
    }
    __syncthreads();

    float acc[8][4];
    const float4 b4 = *(const float4*)(bp2 + c4);
#pragma unroll
    for (int i = 0; i < 8; i++) {
        acc[i][0] = b4.x; acc[i][1] = b4.y; acc[i][2] = b4.z; acc[i][3] = b4.w;
    }
#pragma unroll 4
    for (int k0 = 0; k0 < COUT; k0 += 4) {
        float4 ww[4];
#pragma unroll
        for (int kk = 0; kk < 4; kk++)
            ww[kk] = *(const float4*)(Wp2 + (k0 + kk) * COUT + c4);
#pragma unroll
        for (int i = 0; i < 8; i++) {
            const float4 a = *(const float4*)(us + (r0 + i) * COUT + k0);
            acc[i][0] = fmaf(a.x, ww[0].x, acc[i][0]);
            acc[i][0] = fmaf(a.y, ww[1].x, acc[i][0]);
            acc[i][0] = fmaf(a.z, ww[2].x, acc[i][0]);
            acc[i][0] = fmaf(a.w, ww[3].x, acc[i][0]);
            acc[i][1] = fmaf(a.x, ww[0].y, acc[i][1]);
            acc[i][1] = fmaf(a.y, ww[1].y, acc[i][1]);
            acc[i][1] = fmaf(a.z, ww[2].y, acc[i][1]);
            acc[i][1] = fmaf(a.w, ww[3].y, acc[i][1]);
            acc[i][2] = fmaf(a.x, ww[0].z, acc[i][2]);
            acc[i][2] = fmaf(a.y, ww[1].z, acc[i][2]);
            acc[i][2] = fmaf(a.z, ww[2].z, acc[i][2]);
            acc[i][2] = fmaf(a.w, ww[3].z, acc[i][2]);
            acc[i][3] = fmaf(a.x, ww[0].w, acc[i][3]);
            acc[i][3] = fmaf(a.y, ww[1].w, acc[i][3]);
            acc[i][3] = fmaf(a.z, ww[2].w, acc[i][3]);
            acc[i][3] = fmaf(a.w, ww[3].w, acc[i][3]);
        }
    }
#pragma unroll
    for (int i = 0; i < 8; i++) {
        float* op = out + (size_t)(row0 + r0 + i) * COUT + c4;
        float4 prev = *(const float4*)op;
        float4 o;
        o.x = prev.x + acc[i][0]; o.y = prev.y + acc[i][1];
        o.z = prev.z + acc[i][2]; o.w = prev.w + acc[i][3];
        *(float4*)op = o;
    }
}

// ---------------------------------------------------------------------------
extern "C" void kernel_launch(void* const* d_in, const int* in_sizes, int n_in,
                              void* d_out, int out_size) {
    (void)in_sizes; (void)n_in; (void)out_size;
    const float* x   = (const float*)d_in[0];
    const float* pos = (const float*)d_in[1];
    const float* Wc  = (const float*)d_in[2];
    const float* bc  = (const float*)d_in[3];
    const float* Wn  = (const float*)d_in[4];
    const float* bn  = (const float*)d_in[5];
    const float* Wp1 = (const float*)d_in[6];
    const float* bp1 = (const float*)d_in[7];
    const float* Wp2 = (const float*)d_in[8];
    const float* bp2 = (const float*)d_in[9];
    const float* Wa1 = (const float*)d_in[10];
    const float* ba1 = (const float*)d_in[11];
    const float* Wa2 = (const float*)d_in[12];
    const float* ba2 = (const float*)d_in[13];
    const float* Ws  = (const float*)d_in[14];
    (void)ba2;   // ba2.Ws folds to a softmax-invariant constant -> dropped
    float* out = (float*)d_out;

    cudaFuncSetAttribute(fuse_kernel, cudaFuncAttributeMaxDynamicSharedMemorySize,
                         SMEM_TOTAL);

    prep_kernel<<<65, 256>>>(Wp2, Wa1, Wa2, Ws, bp2, ba1);
    dim3 kgrid(NPTS / 32, BATCH, 2);
    knn_kernel<<<kgrid, 32 * KSPLIT>>>(pos);
    knn_merge_kernel<<<BATCH * NPTS / 256, 256>>>();
    linear_kernel<<<BATCH * NPTS / 32, 128>>>(x, Wc, bc, Wn, bn);
    linw_kernel<<<BATCH * NPTS / 32, 128>>>(Wa1);
    fuse_kernel<<<BATCH * NPTS / PTSB, 256, SMEM_TOTAL>>>(pos, Wp1, bp1, out);
    final_kernel<<<BATCH * NPTS / 32, 128>>>(Wp2, bp2, out);
}